// round 7
// baseline (speedup 1.0000x reference)
#include <cuda_runtime.h>
#include <math.h>

#define NB 64
#define NT 512
#define NVARS 16
#define VDIM 16
#define DD 64
#define NTOK (NB*NT)
#define TPB 512
#define TOKCTA 256
#define SSP 260          // u64 row stride in S (8*SSP % 128B == 32 -> 2-wavefront stores)
#define QS_BIG 1028      // quarter stride (floats) for 64x64 matrices
#define QS_WT  260       // quarter stride (floats) for Wt (16x64)
#define LN_EPS 1e-3f

typedef unsigned long long u64;

// ---------------- packed f32x2 helpers ----------------
#define FMA2(d, a, b) asm("fma.rn.f32x2 %0, %1, %2, %0;" : "+l"(d) : "l"(a), "l"(b))
#define ADD2(d, a, b) asm("add.rn.f32x2 %0, %1, %2;" : "=l"(d) : "l"(a), "l"(b))
#define MUL2(d, a, b) asm("mul.rn.f32x2 %0, %1, %2;" : "=l"(d) : "l"(a), "l"(b))

__device__ __forceinline__ void unpack2(u64 v, float& a, float& b) {
    unsigned int x, y;
    asm("mov.b64 {%0,%1}, %2;" : "=r"(x), "=r"(y) : "l"(v));
    a = __uint_as_float(x); b = __uint_as_float(y);
}
__device__ __forceinline__ u64 pack2(float a, float b) {
    u64 v;
    asm("mov.b64 %0, {%1,%2};" : "=l"(v)
        : "r"(__float_as_uint(a)), "r"(__float_as_uint(b)));
    return v;
}
__device__ __forceinline__ u64 dup2(float a) {
    u64 v;
    asm("mov.b64 %0, {%1,%1};" : "=l"(v) : "r"(__float_as_uint(a)));
    return v;
}

__device__ __forceinline__ float eluf(float x) {
    return x > 0.f ? x : (__expf(x) - 1.f);
}
__device__ __forceinline__ float sigm(float x) {
    return __fdividef(1.f, 1.f + __expf(-x));
}

// smem float offsets
#define OFF_S      0                         // u64[32*260] = 66560 B
#define OFF_W      16640                     // 17488 floats quarter-major
#define OFF_BIAS   (OFF_W + 17488)           // 7*64
#define OFF_CPROJ  (OFF_BIAS + 7*DD)         // 16*64
#define OFF_WSEL   (OFF_CPROJ + NVARS*DD)    // 256*16
#define OFF_CTX    (OFF_WSEL + TOKCTA*NVARS) // 64
#define SMEM_FLOATS (OFF_CTX + DD)
// matrix bases within W_s (floats)
#define WB_T  0
#define WB_P  1040
#define WB_1  5152
#define WB_2  9264
#define WB_G  13376

// acc[j*8+i]: token j (0..1), u64-dim-pair i (dims q*16+2i, q*16+2i+1)
// Activation row permutation: true pair p -> row (p%8)*4 + p/8.
template <int KP>
__device__ __forceinline__ void matvec2t(const float* __restrict__ Wq,
                                         const u64* __restrict__ Sb,
                                         u64 acc[16]) {
#pragma unroll 4
    for (int kp = 0; kp < KP; ++kp) {
        int arow = ((kp & 7) << 2) | (kp >> 3);
        u64 p0 = Sb[arow * SSP];
        u64 p1 = Sb[arow * SSP + 128];
        float x00, x01, x10, x11;
        unpack2(p0, x00, x01);
        unpack2(p1, x10, x11);
        u64 d00 = dup2(x00), d01 = dup2(x01);
        u64 d10 = dup2(x10), d11 = dup2(x11);
        const ulonglong2* w0 = (const ulonglong2*)(Wq + (2 * kp) * 16);
        const ulonglong2* w1 = (const ulonglong2*)(Wq + (2 * kp + 1) * 16);
#pragma unroll
        for (int m = 0; m < 4; ++m) {
            ulonglong2 wa = w0[m];
            FMA2(acc[2 * m],     d00, wa.x); FMA2(acc[2 * m + 1],     d00, wa.y);
            FMA2(acc[8 + 2 * m], d10, wa.x); FMA2(acc[8 + 2 * m + 1], d10, wa.y);
        }
#pragma unroll
        for (int m = 0; m < 4; ++m) {
            ulonglong2 wb = w1[m];
            FMA2(acc[2 * m],     d01, wb.x); FMA2(acc[2 * m + 1],     d01, wb.y);
            FMA2(acc[8 + 2 * m], d11, wb.x); FMA2(acc[8 + 2 * m + 1], d11, wb.y);
        }
    }
}

__device__ __forceinline__ void load_bias2(const float* __restrict__ bsm, int q,
                                           u64 acc[16]) {
    const u64* b = (const u64*)(bsm + q * 16);
#pragma unroll
    for (int i = 0; i < 8; i++) {
        u64 v = b[i];
        acc[i] = v;
        acc[8 + i] = v;
    }
}

// thread (q) local pair i lives at row i*4+q; token j at col offset 128*j
__device__ __forceinline__ void store_stage2(u64* __restrict__ S, int col, int q,
                                             const u64 acc[16]) {
#pragma unroll
    for (int i = 0; i < 8; i++) {
        int r = (i * 4 + q) * SSP + col;
        S[r] = acc[i];
        S[r + 128] = acc[8 + i];
    }
}

// ---------------------------------------------------------------------------
__global__ __launch_bounds__(TPB, 1) void vsn_fused_kernel(
    const float* __restrict__ inputs, const float* __restrict__ context,
    const float* __restrict__ Wt, const float* __restrict__ bt,
    const float* __restrict__ Wctx,
    const float* __restrict__ W1, const float* __restrict__ b1,
    const float* __restrict__ W2, const float* __restrict__ b2,
    const float* __restrict__ Wg, const float* __restrict__ bg,
    const float* __restrict__ Wp, const float* __restrict__ bp,
    const float* __restrict__ gamma_, const float* __restrict__ beta_,
    const float* __restrict__ Ws, const float* __restrict__ bs,
    float* __restrict__ selected, float* __restrict__ wout) {
    extern __shared__ __align__(16) float smem[];
    u64* S = (u64*)(smem + OFF_S);
    float* W_s = smem + OFF_W;
    float* bias_s = smem + OFF_BIAS;
    float* cproj_s = smem + OFF_CPROJ;
    float* wsel_s = smem + OFF_WSEL;
    float* ctx_s = smem + OFF_CTX;

    const int tid = threadIdx.x;
    const int slot = tid >> 2;     // 0..127 token column
    const int q = tid & 3;         // dim quarter
    const int base = blockIdx.x * TOKCTA;
    const int b = base / NT;

    // ---------- phase 0: stage Ws/bs/ctx ----------
    {
        const float4* s = (const float4*)Ws;
        float4* d = (float4*)W_s;
        for (int i = tid; i < 1024; i += TPB) d[i] = s[i];
        if (tid < 16) bias_s[tid] = bs[tid];
        if (tid >= 32 && tid < 32 + DD) ctx_s[tid - 32] = context[(size_t)b * DD + tid - 32];
    }
    __syncthreads();

    if (tid < 256) {
        // ---------- phase 1a: softmax for token base+tid ----------
        int token = base + tid;
        const float4* xp = (const float4*)(inputs + (size_t)token * 256);
        u64 lg[8];
#pragma unroll
        for (int j = 0; j < 8; j++) lg[j] = ((const u64*)bias_s)[j];
#pragma unroll 4
        for (int f4 = 0; f4 < 64; ++f4) {
            float4 xv = xp[f4];
            const float* wr = W_s + f4 * 64;
#pragma unroll
            for (int c = 0; c < 4; c++) {
                float x = (c == 0) ? xv.x : (c == 1) ? xv.y : (c == 2) ? xv.z : xv.w;
                u64 x2 = dup2(x);
                const u64* w2 = (const u64*)(wr + c * 16);
#pragma unroll
                for (int j = 0; j < 8; j++) FMA2(lg[j], x2, w2[j]);
            }
        }
        float l[16];
#pragma unroll
        for (int j = 0; j < 8; j++) unpack2(lg[j], l[2 * j], l[2 * j + 1]);
        float mx = l[0];
#pragma unroll
        for (int i = 1; i < 16; i++) mx = fmaxf(mx, l[i]);
        float sum = 0.f;
#pragma unroll
        for (int i = 0; i < 16; i++) { l[i] = __expf(l[i] - mx); sum += l[i]; }
        float inv = __fdividef(1.f, sum);
        float4* gp = (float4*)(wout + (size_t)token * 16);
        float4* sp = (float4*)(wsel_s + tid * 16);
#pragma unroll
        for (int j = 0; j < 4; j++) {
            float4 o;
            o.x = l[4 * j + 0] * inv; o.y = l[4 * j + 1] * inv;
            o.z = l[4 * j + 2] * inv; o.w = l[4 * j + 3] * inv;
            gp[j] = o;
            sp[j] = o;
        }
    } else {
        // ---------- phase 1b: cproj for this CTA's batch row ----------
        int t2 = tid - 256;
        int n = t2 >> 4;
        int e = (t2 & 15) * 4;
        const float* W = Wctx + (size_t)n * DD * DD;
        float4 acc = make_float4(0.f, 0.f, 0.f, 0.f);
#pragma unroll 8
        for (int d = 0; d < DD; ++d) {
            float c = ctx_s[d];
            float4 w = *(const float4*)(W + d * DD + e);
            acc.x = fmaf(c, w.x, acc.x); acc.y = fmaf(c, w.y, acc.y);
            acc.z = fmaf(c, w.z, acc.z); acc.w = fmaf(c, w.w, acc.w);
        }
        *(float4*)(cproj_s + n * DD + e) = acc;
    }

    u64 sel[16];
#pragma unroll
    for (int i = 0; i < 16; i++) sel[i] = 0ull;

    const u64* Sb = S + slot;
    const int col = slot;

    for (int n = 0; n < NVARS; ++n) {
        __syncthreads();
        // quarter-major weight staging
        {
            const float4* s0 = (const float4*)(Wt + (size_t)n * VDIM * DD);
            float4* d0 = (float4*)(W_s + WB_T);
            for (int i = tid; i < 256; i += TPB) {
                int row = i >> 4, c = i & 15;
                d0[(c >> 2) * (QS_WT / 4) + row * 4 + (c & 3)] = s0[i];
            }
            const float* srcs[4] = {Wp + (size_t)n * DD * DD, W1 + (size_t)n * DD * DD,
                                    W2 + (size_t)n * DD * DD, Wg + (size_t)n * DD * DD};
            const int bases[4] = {WB_P, WB_1, WB_2, WB_G};
#pragma unroll
            for (int jm = 0; jm < 4; jm++) {
                const float4* sj = (const float4*)srcs[jm];
                float4* dj = (float4*)(W_s + bases[jm]);
                for (int i = tid; i < 1024; i += TPB) {
                    int row = i >> 4, c = i & 15;
                    dj[(c >> 2) * (QS_BIG / 4) + row * 4 + (c & 3)] = sj[i];
                }
            }
        }
        if (tid < DD) {
            bias_s[0 * DD + tid] = bt[n * DD + tid];
            bias_s[1 * DD + tid] = bp[n * DD + tid];
            bias_s[2 * DD + tid] = b1[n * DD + tid];
            bias_s[3 * DD + tid] = b2[n * DD + tid];
            bias_s[4 * DD + tid] = bg[n * DD + tid];
            bias_s[5 * DD + tid] = gamma_[n * DD + tid];
            bias_s[6 * DD + tid] = beta_[n * DD + tid];
        }
        __syncthreads();

        // stage x slices: thread q loads dims [q*4,q*4+4) (true pairs 2q,2q+1
        // -> rows 8q, 8q+4) for tokens slot, slot+128
#pragma unroll
        for (int j = 0; j < 2; j++) {
            int tok = base + slot + 128 * j;
            float4 v = *(const float4*)(inputs + (size_t)tok * 256 + n * VDIM + q * 4);
            S[(8 * q) * SSP + col + 128 * j] = pack2(v.x, v.y);
            S[(8 * q + 4) * SSP + col + 128 * j] = pack2(v.z, v.w);
        }
        __syncwarp();

        const float* Wq_t = W_s + WB_T + q * QS_WT;
        const float* Wq_p = W_s + WB_P + q * QS_BIG;
        const float* Wq_1 = W_s + WB_1 + q * QS_BIG;
        const float* Wq_2 = W_s + WB_2 + q * QS_BIG;
        const float* Wq_g = W_s + WB_G + q * QS_BIG;

        u64 acc[16], res[16];
        // t = x @ Wt + bt
        load_bias2(bias_s + 0 * DD, q, acc);
        matvec2t<8>(Wq_t, Sb, acc);
        __syncwarp();
        store_stage2(S, col, q, acc);      // S = t (acc keeps t)
        __syncwarp();
        // residual = t @ Wp + bp  (stays in registers)
        load_bias2(bias_s + 1 * DD, q, res);
        matvec2t<32>(Wq_p, Sb, res);
        __syncwarp();                       // Wp reads of t done
        // a = t + cproj
        {
            const u64* cp = (const u64*)(cproj_s + n * DD + q * 16);
#pragma unroll
            for (int i = 0; i < 8; i++) {
                u64 c = cp[i];
                ADD2(acc[i], acc[i], c);
                ADD2(acc[8 + i], acc[8 + i], c);
            }
        }
        store_stage2(S, col, q, acc);      // S = a
        __syncwarp();
        // h1 = elu(a @ W1 + b1)
        load_bias2(bias_s + 2 * DD, q, acc);
        matvec2t<32>(Wq_1, Sb, acc);
#pragma unroll
        for (int i = 0; i < 16; i++) {
            float e0, e1;
            unpack2(acc[i], e0, e1);
            acc[i] = pack2(eluf(e0), eluf(e1));
        }
        __syncwarp();
        store_stage2(S, col, q, acc);      // S = h1
        __syncwarp();
        // h2 = h1 @ W2 + b2
        load_bias2(bias_s + 3 * DD, q, acc);
        matvec2t<32>(Wq_2, Sb, acc);
        __syncwarp();
        store_stage2(S, col, q, acc);      // S = h2
        __syncwarp();
        // gate logits -> y = residual + sigmoid(g)*h2
        load_bias2(bias_s + 4 * DD, q, acc);
        matvec2t<32>(Wq_g, Sb, acc);
#pragma unroll
        for (int j = 0; j < 2; j++) {
#pragma unroll
            for (int i = 0; i < 8; i++) {
                int r = (i * 4 + q) * SSP + col + 128 * j;
                float g0, g1;
                unpack2(acc[j * 8 + i], g0, g1);
                u64 gpk = pack2(sigm(g0), sigm(g1));
                u64 y = res[j * 8 + i];
                FMA2(y, gpk, S[r]);        // y = res + gate*h2
                acc[j * 8 + i] = y;
            }
        }
        // LayerNorm (4-lane butterfly) + weighted select
        const u64* g64 = (const u64*)(bias_s + 5 * DD + q * 16);
        const u64* be64 = (const u64*)(bias_s + 6 * DD + q * 16);
#pragma unroll
        for (int j = 0; j < 2; j++) {
            u64* a = acc + j * 8;
            u64 s2 = a[0];
#pragma unroll
            for (int i = 1; i < 8; i++) ADD2(s2, s2, a[i]);
            float sa, sb; unpack2(s2, sa, sb);
            float part = sa + sb;
            part += __shfl_xor_sync(0xffffffffu, part, 1);
            part += __shfl_xor_sync(0xffffffffu, part, 2);
            float mu = part * (1.f / 64.f);
            u64 negmu = dup2(-mu);
            u64 v2 = 0ull;
#pragma unroll
            for (int i = 0; i < 8; i++) {
                u64 d; ADD2(d, a[i], negmu); FMA2(v2, d, d);
            }
            float va, vb; unpack2(v2, va, vb);
            float vpart = va + vb;
            vpart += __shfl_xor_sync(0xffffffffu, vpart, 1);
            vpart += __shfl_xor_sync(0xffffffffu, vpart, 2);
            float var = vpart * (1.f / 64.f);
            u64 rs2 = dup2(rsqrtf(var + LN_EPS));
            u64 w2 = dup2(wsel_s[(slot + 128 * j) * NVARS + n]);
#pragma unroll
            for (int i = 0; i < 8; i++) {
                u64 d, t2, y;
                ADD2(d, a[i], negmu);
                MUL2(t2, d, rs2);
                y = be64[i];
                FMA2(y, t2, g64[i]);
                FMA2(sel[j * 8 + i], w2, y);
            }
        }
    }

    // output: 16 dims x 2 tokens
#pragma unroll
    for (int j = 0; j < 2; j++) {
        int tok = base + slot + 128 * j;
        ulonglong2* op = (ulonglong2*)(selected + (size_t)tok * DD + q * 16);
#pragma unroll
        for (int m = 0; m < 4; m++) {
            ulonglong2 o;
            o.x = sel[j * 8 + 2 * m];
            o.y = sel[j * 8 + 2 * m + 1];
            op[m] = o;
        }
    }
}

// ---------------------------------------------------------------------------
extern "C" void kernel_launch(void* const* d_in, const int* in_sizes, int n_in,
                              void* d_out, int out_size) {
    const float* inputs  = (const float*)d_in[0];
    const float* context = (const float*)d_in[1];
    const float* Wt   = (const float*)d_in[2];
    const float* bt   = (const float*)d_in[3];
    const float* Wctx = (const float*)d_in[4];
    const float* W1   = (const float*)d_in[5];
    const float* b1   = (const float*)d_in[6];
    const float* W2   = (const float*)d_in[7];
    const float* b2   = (const float*)d_in[8];
    const float* Wg   = (const float*)d_in[9];
    const float* bg   = (const float*)d_in[10];
    const float* Wp   = (const float*)d_in[11];
    const float* bp   = (const float*)d_in[12];
    const float* gam  = (const float*)d_in[13];
    const float* bet  = (const float*)d_in[14];
    const float* Ws   = (const float*)d_in[15];
    const float* bs   = (const float*)d_in[16];

    float* selected = (float*)d_out;
    float* wout = selected + (size_t)NTOK * DD;

    size_t smem_bytes = (size_t)SMEM_FLOATS * sizeof(float);
    cudaFuncSetAttribute(vsn_fused_kernel,
                         cudaFuncAttributeMaxDynamicSharedMemorySize,
                         (int)smem_bytes);
    vsn_fused_kernel<<<NTOK / TOKCTA, TPB, smem_bytes>>>(
        inputs, context, Wt, bt, Wctx, W1, b1, W2, b2, Wg, bg, Wp, bp,
        gam, bet, Ws, bs, selected, wout);
}

// round 9
// speedup vs baseline: 2.4168x; 2.4168x over previous
#include <cuda_runtime.h>
#include <cuda_bf16.h>
#include <math.h>

#define NB 64
#define NT 512
#define NVARS 16
#define VDIM 16
#define DD 64
#define NTOK (NB*NT)
#define TPB 256
#define MTILE 128
#define LN_EPS 1e-3f

typedef unsigned long long u64;
typedef unsigned int u32;

// prepped weights: per var 9 tiles x 8192B (swizzled [n][k] bf16, 128B rows)
#define WPV_BYTES 73728
__device__ __align__(16) char g_wprep[NVARS * WPV_BYTES];
__device__ __align__(16) float g_cproj[NB * NVARS * DD];

// tile byte offsets (within a var's prepped block / within smem)
#define WT_OFF 0
#define WP_HI 8192
#define WP_LO 16384
#define W1_HI 24576
#define W1_LO 32768
#define W2_HI 40960
#define W2_LO 49152
#define WG_HI 57344
#define WG_LO 65536
// smem byte offsets
#define BIAS_OFF  73728     // 7 x 64 floats
#define CPROJ_OFF 75520     // 64 floats
#define WSEL_OFF  75776     // 128 x 16 floats
#define SMEM_TOTAL 83968

// ---------------- ptx helpers ----------------
__device__ __forceinline__ u32 smem_u32(const void* p) {
    u32 a;
    asm("{ .reg .u64 t; cvta.to.shared.u64 t, %1; cvt.u32.u64 %0, t; }"
        : "=r"(a) : "l"(p));
    return a;
}

#define LDMX4(r0, r1, r2, r3, addr) \
    asm volatile("ldmatrix.sync.aligned.m8n8.x4.shared.b16 {%0,%1,%2,%3}, [%4];" \
                 : "=r"(r0), "=r"(r1), "=r"(r2), "=r"(r3) : "r"(addr))

__device__ __forceinline__ void mma16816(float* d, u32 a0, u32 a1, u32 a2, u32 a3,
                                         u32 b0, u32 b1) {
    asm volatile(
        "mma.sync.aligned.m16n8k16.row.col.f32.bf16.bf16.f32 "
        "{%0,%1,%2,%3},{%4,%5,%6,%7},{%8,%9},{%0,%1,%2,%3};"
        : "+f"(d[0]), "+f"(d[1]), "+f"(d[2]), "+f"(d[3])
        : "r"(a0), "r"(a1), "r"(a2), "r"(a3), "r"(b0), "r"(b1));
}

// pack (e0, e1) -> bf16x2 with e0 in LOW half
__device__ __forceinline__ u32 pkpair(float e0, float e1) {
    u32 r;
    asm("cvt.rn.bf16x2.f32 %0, %1, %2;" : "=r"(r) : "f"(e1), "f"(e0));
    return r;
}
__device__ __forceinline__ u32 pklo(u32 h, float e0, float e1) {
    float h0 = __uint_as_float(h << 16);
    float h1 = __uint_as_float(h & 0xffff0000u);
    return pkpair(e0 - h0, e1 - h1);
}
__device__ __forceinline__ float flo(u32 r) { return __uint_as_float(r << 16); }
__device__ __forceinline__ float fhi(u32 r) { return __uint_as_float(r & 0xffff0000u); }

__device__ __forceinline__ float sigm(float x) {
    return __fdividef(1.f, 1.f + __expf(-x));
}

// D[32] -> A fragments (hi/lo), layout: fh[4*kt + {0..3}]
__device__ __forceinline__ void d_to_frag(const float* D, u32* fh, u32* fl) {
#pragma unroll
    for (int kt = 0; kt < 4; kt++) {
        const float* d0 = D + (2 * kt) * 4;
        const float* d1 = D + (2 * kt + 1) * 4;
        u32 h;
        h = pkpair(d0[0], d0[1]); fh[4*kt+0] = h; fl[4*kt+0] = pklo(h, d0[0], d0[1]);
        h = pkpair(d0[2], d0[3]); fh[4*kt+1] = h; fl[4*kt+1] = pklo(h, d0[2], d0[3]);
        h = pkpair(d1[0], d1[1]); fh[4*kt+2] = h; fl[4*kt+2] = pklo(h, d1[0], d1[1]);
        h = pkpair(d1[2], d1[3]); fh[4*kt+3] = h; fl[4*kt+3] = pklo(h, d1[2], d1[3]);
    }
}

// init D with per-column bias (broadcast across rows)
__device__ __forceinline__ void d_init(float* D, const float* bvec, int tig) {
#pragma unroll
    for (int j = 0; j < 8; j++) {
        float2 bv = *(const float2*)(bvec + 8 * j + 2 * tig);
        D[4*j+0] = bv.x; D[4*j+1] = bv.y; D[4*j+2] = bv.x; D[4*j+3] = bv.y;
    }
}

// one 64x64 layer: D += (Ahi+Alo) @ (Whi+Wlo)^T  (3-product split)
__device__ __forceinline__ void do_layer(u32 base_hi, u32 base_lo,
                                         const u32* fh, const u32* fl,
                                         float* D, int rowin, int m) {
    const u32 sw = (u32)(rowin << 4);
    const u32 rb = (u32)((m >> 1) * 1024 + rowin * 128);
#pragma unroll
    for (int kt = 0; kt < 4; kt++) {
        u32 csw = ((u32)(32 * kt + 16 * (m & 1))) ^ sw;
        const u32* ah = fh + 4 * kt;
        const u32* al = fl + 4 * kt;
#pragma unroll
        for (int p = 0; p < 4; p++) {
            u32 off = rb + (u32)(p * 2048) + csw;
            u32 bh0, bh1, bh2, bh3, bl0, bl1, bl2, bl3;
            LDMX4(bh0, bh1, bh2, bh3, base_hi + off);
            LDMX4(bl0, bl1, bl2, bl3, base_lo + off);
            mma16816(D + 8*p,     ah[0], ah[1], ah[2], ah[3], bh0, bh1);
            mma16816(D + 8*p,     ah[0], ah[1], ah[2], ah[3], bl0, bl1);
            mma16816(D + 8*p,     al[0], al[1], al[2], al[3], bh0, bh1);
            mma16816(D + 8*p + 4, ah[0], ah[1], ah[2], ah[3], bh2, bh3);
            mma16816(D + 8*p + 4, ah[0], ah[1], ah[2], ah[3], bl2, bl3);
            mma16816(D + 8*p + 4, al[0], al[1], al[2], al[3], bh2, bh3);
        }
    }
}

// ---------------------------------------------------------------------------
// prep: transpose + hi/lo split weights into swizzled [n][k] tiles
// ---------------------------------------------------------------------------
__global__ void prep_weights_kernel(const float* __restrict__ Wt,
                                    const float* __restrict__ Wp,
                                    const float* __restrict__ W1,
                                    const float* __restrict__ W2,
                                    const float* __restrict__ Wg) {
    int n = blockIdx.x;
    char* dst = g_wprep + (size_t)n * WPV_BYTES;
    // Wt: src [v=16][d=64] -> tile rows n=d, cols k=v; hi at cs 0/16, lo at 32/48
    for (int e = threadIdx.x; e < VDIM * DD; e += blockDim.x) {
        int d = e & 63, v = e >> 6;
        float w = Wt[(size_t)n * VDIM * DD + v * DD + d];
        __nv_bfloat16 hb = __float2bfloat16(w);
        __nv_bfloat16 lb = __float2bfloat16(w - __bfloat162float(hb));
        u32 cs = (u32)(16 * (v >> 3));
        u32 swx = ((u32)(d & 7)) << 4;
        u32 base = (u32)(d * 128) + (u32)((v & 7) * 2);
        *(__nv_bfloat16*)(dst + WT_OFF + base + (cs ^ swx)) = hb;
        *(__nv_bfloat16*)(dst + WT_OFF + base + ((cs + 32) ^ swx)) = lb;
    }
    const float* srcs[4] = {Wp + (size_t)n * DD * DD, W1 + (size_t)n * DD * DD,
                            W2 + (size_t)n * DD * DD, Wg + (size_t)n * DD * DD};
    const int hioff[4] = {WP_HI, W1_HI, W2_HI, WG_HI};
    for (int mm = 0; mm < 4; mm++) {
        const float* s = srcs[mm];
        char* th = dst + hioff[mm];
        char* tl = th + 8192;
        for (int e = threadIdx.x; e < DD * DD; e += blockDim.x) {
            int d = e & 63, k = e >> 6;
            float w = s[k * DD + d];
            __nv_bfloat16 hb = __float2bfloat16(w);
            __nv_bfloat16 lb = __float2bfloat16(w - __bfloat162float(hb));
            u32 cs = (u32)(16 * (k >> 3));
            u32 swx = ((u32)(d & 7)) << 4;
            u32 addr = (u32)(d * 128) + (cs ^ swx) + (u32)((k & 7) * 2);
            *(__nv_bfloat16*)(th + addr) = hb;
            *(__nv_bfloat16*)(tl + addr) = lb;
        }
    }
}

// ---------------------------------------------------------------------------
__global__ void cproj_kernel(const float* __restrict__ context,
                             const float* __restrict__ Wctx) {
    int bb = blockIdx.x, n = blockIdx.y, e = threadIdx.x;
    const float* ctx = context + bb * DD;
    const float* W = Wctx + (size_t)n * DD * DD;
    float acc = 0.f;
#pragma unroll 8
    for (int d = 0; d < DD; ++d)
        acc = fmaf(ctx[d], W[d * DD + e], acc);
    g_cproj[((size_t)bb * NVARS + n) * DD + e] = acc;
}

// ---------------------------------------------------------------------------
__global__ __launch_bounds__(256) void weights_kernel(
    const float* __restrict__ inputs, const float* __restrict__ Ws,
    const float* __restrict__ bs, float* __restrict__ wout) {
    __shared__ __align__(16) float ws_s[256 * 16];
    __shared__ __align__(16) float bs_s[16];
    int tid = threadIdx.x;
    for (int i = tid; i < 256 * 16; i += 256) ws_s[i] = Ws[i];
    if (tid < 16) bs_s[tid] = bs[tid];
    __syncthreads();

    int token = blockIdx.x * 256 + tid;
    const float4* xp = (const float4*)(inputs + (size_t)token * 256);
    float l[16];
#pragma unroll
    for (int i = 0; i < 16; i++) l[i] = bs_s[i];
#pragma unroll 4
    for (int f4 = 0; f4 < 64; ++f4) {
        float4 xv = xp[f4];
        const float* wr = ws_s + f4 * 64;
#pragma unroll
        for (int c = 0; c < 4; c++) {
            float x = (c == 0) ? xv.x : (c == 1) ? xv.y : (c == 2) ? xv.z : xv.w;
            const float* w = wr + c * 16;
#pragma unroll
            for (int i = 0; i < 16; i++) l[i] = fmaf(x, w[i], l[i]);
        }
    }
    float mx = l[0];
#pragma unroll
    for (int i = 1; i < 16; i++) mx = fmaxf(mx, l[i]);
    float s = 0.f;
#pragma unroll
    for (int i = 0; i < 16; i++) { l[i] = __expf(l[i] - mx); s += l[i]; }
    float inv = __fdividef(1.f, s);
    float4* op = (float4*)(wout + (size_t)token * 16);
#pragma unroll
    for (int j = 0; j < 4; j++)
        op[j] = make_float4(l[4*j] * inv, l[4*j+1] * inv, l[4*j+2] * inv, l[4*j+3] * inv);
}

// ---------------------------------------------------------------------------
// main: 128-token tile per CTA, mma.sync chain, register-resident activations
// ---------------------------------------------------------------------------
__global__ __launch_bounds__(TPB, 1) void vsn_mma_kernel(
    const float* __restrict__ inputs,
    const float* __restrict__ bt, const float* __restrict__ b1,
    const float* __restrict__ b2, const float* __restrict__ bg,
    const float* __restrict__ bp,
    const float* __restrict__ gamma_, const float* __restrict__ beta_,
    const float* __restrict__ wsel, float* __restrict__ selected) {
    extern __shared__ __align__(128) char sm[];
    const int tid = threadIdx.x;
    const int wid = tid >> 5, lane = tid & 31;
    const int gid = lane >> 2, tig = lane & 3;
    const int rowin = lane & 7, mq = lane >> 3;
    const int row0 = wid * 16 + gid, row1 = row0 + 8;
    const int base = blockIdx.x * MTILE;
    const int bb = base / NT;
    const int tok0 = base + row0, tok1 = base + row1;

    const u32 smb = smem_u32(sm);
    float* bias_s  = (float*)(sm + BIAS_OFF);
    float* cproj_s = (float*)(sm + CPROJ_OFF);
    float* wsel_s  = (float*)(sm + WSEL_OFF);

    // stage selection weights once
    for (int i = tid; i < MTILE * NVARS; i += TPB)
        wsel_s[i] = wsel[(size_t)base * NVARS + i];

    float sel[32];
#pragma unroll
    for (int i = 0; i < 32; i++) sel[i] = 0.f;

    for (int n = 0; n < NVARS; ++n) {
        __syncthreads();   // previous var's smem reads done (covers wsel at n=0)
        // ---- stage weights (flat copy; prep already swizzled) ----
        {
            const uint4* src = (const uint4*)(g_wprep + (size_t)n * WPV_BYTES);
            uint4* d = (uint4*)sm;
#pragma unroll 6
            for (int i = tid; i < WPV_BYTES / 16; i += TPB) d[i] = src[i];
        }
        if (tid < DD) {
            bias_s[0 * DD + tid] = bt[n * DD + tid];
            bias_s[1 * DD + tid] = b1[n * DD + tid];
            bias_s[2 * DD + tid] = b2[n * DD + tid];
            bias_s[3 * DD + tid] = bg[n * DD + tid];
            bias_s[4 * DD + tid] = bp[n * DD + tid];
            bias_s[5 * DD + tid] = gamma_[n * DD + tid];
            bias_s[6 * DD + tid] = beta_[n * DD + tid];
            cproj_s[tid] = g_cproj[((size_t)bb * NVARS + n) * DD + tid];
        }
        __syncthreads();

        // ---- layer 1: t = x @ Wt + bt  (k = 16) ----
        float D[32];
        d_init(D, bias_s + 0 * DD, tig);
        {
            // x fragments
            const float* xb0 = inputs + (size_t)tok0 * 256 + n * VDIM;
            const float* xb1 = inputs + (size_t)tok1 * 256 + n * VDIM;
            float2 x00 = *(const float2*)(xb0 + 2 * tig);
            float2 x10 = *(const float2*)(xb1 + 2 * tig);
            float2 x01 = *(const float2*)(xb0 + 8 + 2 * tig);
            float2 x11 = *(const float2*)(xb1 + 8 + 2 * tig);
            u32 axh[4], axl[4];
            axh[0] = pkpair(x00.x, x00.y); axl[0] = pklo(axh[0], x00.x, x00.y);
            axh[1] = pkpair(x10.x, x10.y); axl[1] = pklo(axh[1], x10.x, x10.y);
            axh[2] = pkpair(x01.x, x01.y); axl[2] = pklo(axh[2], x01.x, x01.y);
            axh[3] = pkpair(x11.x, x11.y); axl[3] = pklo(axh[3], x11.x, x11.y);

            const u32 sw = (u32)(rowin << 4);
            const u32 rb = (u32)((mq >> 1) * 1024 + rowin * 128);
            u32 csh = ((u32)(16 * (mq & 1))) ^ sw;
            u32 csl = ((u32)(32 + 16 * (mq & 1))) ^ sw;
#pragma unroll
            for (int p = 0; p < 4; p++) {
                u32 off = rb + (u32)(p * 2048);
                u32 bh0, bh1, bh2, bh3, bl0, bl1, bl2, bl3;
                LDMX4(bh0, bh1, bh2, bh3, smb + WT_OFF + off + csh);
                LDMX4(bl0, bl1, bl2, bl3, smb + WT_OFF + off + csl);
                mma16816(D + 8*p,     axh[0], axh[1], axh[2], axh[3], bh0, bh1);
                mma16816(D + 8*p,     axh[0], axh[1], axh[2], axh[3], bl0, bl1);
                mma16816(D + 8*p,     axl[0], axl[1], axl[2], axl[3], bh0, bh1);
                mma16816(D + 8*p + 4, axh[0], axh[1], axh[2], axh[3], bh2, bh3);
                mma16816(D + 8*p + 4, axh[0], axh[1], axh[2], axh[3], bl2, bl3);
                mma16816(D + 8*p + 4, axl[0], axl[1], axl[2], axl[3], bh2, bh3);
            }
        }

        u32 fh[16], fl[16];
        d_to_frag(D, fh, fl);      // t fragments

        // ---- residual = t @ Wp + bp (kept in Dres regs) ----
        float Dres[32];
        d_init(Dres, bias_s + 4 * DD, tig);
        do_layer(smb + WP_HI, smb + WP_LO, fh, fl, Dres, rowin, mq);

        // ---- a = t + cproj -> fragments ----
#pragma unroll
        for (int j = 0; j < 8; j++) {
            float2 cp = *(const float2*)(cproj_s + 8 * j + 2 * tig);
            D[4*j+0] += cp.x; D[4*j+1] += cp.y;
            D[4*j+2] += cp.x; D[4*j+3] += cp.y;
        }
        d_to_frag(D, fh, fl);

        // ---- h1 = elu(a @ W1 + b1) ----
        d_init(D, bias_s + 1 * DD, tig);
        do_layer(smb + W1_HI, smb + W1_LO, fh, fl, D, rowin, mq);
#pragma unroll
        for (int i = 0; i < 32; i++) {
            float x = D[i];
            D[i] = x > 0.f ? x : (__expf(x) - 1.f);
        }
        d_to_frag(D, fh, fl);

        // ---- h2 = h1 @ W2 + b2 ----
        d_init(D, bias_s + 2 * DD, tig);
        do_layer(smb + W2_HI, smb + W2_LO, fh, fl, D, rowin, mq);
        d_to_frag(D, fh, fl);      // h2 fragments (h2 value = hi + lo)

        // ---- gate logits = h2 @ Wg + bg ----
        d_init(D, bias_s + 3 * DD, tig);
        do_layer(smb + WG_HI, smb + WG_LO, fh, fl, D, rowin, mq);

        // ---- y = res + sigmoid(g)*h2; LayerNorm; weighted select ----
        float sum0 = 0.f, sq0 = 0.f, sum1 = 0.f, sq1 = 0.f;
#pragma unroll
        for (int j = 0; j < 8; j++) {
            int o = 4 * (j >> 1) + 2 * (j & 1);
            u32 h0 = fh[o], l0 = fl[o], h1r = fh[o + 1], l1r = fl[o + 1];
            float h2a = flo(h0) + flo(l0), h2b = fhi(h0) + fhi(l0);
            float h2c = flo(h1r) + flo(l1r), h2d = fhi(h1r) + fhi(l1r);
            float y0 = fmaf(sigm(D[4*j+0]), h2a, Dres[4*j+0]);
            float y1 = fmaf(sigm(D[4*j+1]), h2b, Dres[4*j+1]);
            float y2 = fmaf(sigm(D[4*j+2]), h2c, Dres[4*j+2]);
            float y3 = fmaf(sigm(D[4*j+3]), h2d, Dres[4*j+3]);
            D[4*j+0] = y0; D[4*j+1] = y1; D[4*j+2] = y2; D[4*j+3] = y3;
            sum0 += y0 + y1; sq0 = fmaf(y0, y0, fmaf(y1, y1, sq0));
            sum1 += y2 + y3; sq1 = fmaf(y2, y2, fmaf(y3, y3, sq1));
        }
        sum0 += __shfl_xor_sync(0xffffffffu, sum0, 1);
        sum0 += __shfl_xor_sync(0xffffffffu, sum0, 2);
        sq0  += __shfl_xor_sync(0xffffffffu, sq0, 1);
        sq0  += __shfl_xor_sync(0xffffffffu, sq0, 2);
        sum1 += __shfl_xor_sync(0xffffffffu, sum1, 1);
        sum1 += __shfl_xor_sync(0xffffffffu, sum1, 2);
        sq1  += __shfl_xor_sync(0xffffffffu, sq1, 1);
        sq1  += __shfl_xor_sync(0xffffffffu, sq1, 2);
        float mu0 = sum0 * (1.f / 64.f);
        float rs0 = rsqrtf(sq0 * (1.f / 64.f) - mu0 * mu0 + LN_EPS);
        float mu1 = sum1 * (1.f / 64.f);
        float rs1 = rsqrtf(sq1 * (1.f / 64.f) - mu1 * mu1 + LN_EPS);
        float w0 = wsel_s[row0 * NVARS + n];
        float w1 = wsel_s[row1 * NVARS + n];
#pragma unroll
        for (int j = 0; j < 8; j++) {
            float2 gm = *(const float2*)(bias_s + 5 * DD + 8 * j + 2 * tig);
            float2 be = *(const float2*)(bias_s + 6 * DD + 8 * j + 2 * tig);
            float yn0 = fmaf((D[4*j+0] - mu0) * rs0, gm.x, be.x);
            float yn1 = fmaf((D[4*j+1] - mu0) * rs0, gm.y, be.y);
            float yn2 = fmaf((D[4*j+2] - mu1) * rs1, gm.x, be.x);
            float yn3 = fmaf((D[4*j+3] - mu1) * rs1, gm.y, be.y);
            sel[4*j+0] = fmaf(w0, yn0, sel[4*j+0]);
            sel[4*j+1] = fmaf(w0, yn1, sel[4*j+1]);
            sel[4*j+2] = fmaf(w1, yn2, sel[4*j+2]);
            sel[4*j+3] = fmaf(w1, yn3, sel[4*j+3]);
        }
    }

    // ---- output ----
#pragma unroll
    for (int j = 0; j < 8; j++) {
        *(float2*)(selected + (size_t)tok0 * DD + 8 * j + 2 * tig)
            = make_float2(sel[4*j+0], sel[4*j+1]);
        *(float2*)(selected + (size_t)tok1 * DD + 8 * j + 2 * tig)
            = make_float2(sel[4*j+2], sel[4*j+3]);
    }
}

// ---------------------------------------------------------------------------
extern "C" void kernel_launch(void* const* d_in, const int* in_sizes, int n_in,
                              void* d_out, int out_size) {
    const float* inputs  = (const float*)d_in[0];
    const float* context = (const float*)d_in[1];
    const float* Wt   = (const float*)d_in[2];
    const float* bt   = (const float*)d_in[3];
    const float* Wctx = (const float*)d_in[4];
    const float* W1   = (const float*)d_in[5];
    const float* b1   = (const float*)d_in[6];
    const float* W2   = (const float*)d_in[7];
    const float* b2   = (const float*)d_in[8];
    const float* Wg   = (const float*)d_in[9];
    const float* bg   = (const float*)d_in[10];
    const float* Wp   = (const float*)d_in[11];
    const float* bp   = (const float*)d_in[12];
    const float* gam  = (const float*)d_in[13];
    const float* bet  = (const float*)d_in[14];
    const float* Ws   = (const float*)d_in[15];
    const float* bs   = (const float*)d_in[16];

    float* selected = (float*)d_out;
    float* wout = selected + (size_t)NTOK * DD;

    prep_weights_kernel<<<NVARS, 256>>>(Wt, Wp, W1, W2, Wg);
    cproj_kernel<<<dim3(NB, NVARS), DD>>>(context, Wctx);
    weights_kernel<<<NTOK / 256, 256>>>(inputs, Ws, bs, wout);

    cudaFuncSetAttribute(vsn_mma_kernel,
                         cudaFuncAttributeMaxDynamicSharedMemorySize, SMEM_TOTAL);
    vsn_mma_kernel<<<NTOK / MTILE, TPB, SMEM_TOTAL>>>(
        inputs, bt, b1, b2, bg, bp, gam, bet, wout, selected);
}

// round 10
// speedup vs baseline: 2.7251x; 1.1276x over previous
#include <cuda_runtime.h>
#include <cuda_bf16.h>
#include <math.h>

#define NB 64
#define NT 512
#define NVARS 16
#define VDIM 16
#define DD 64
#define NTOK (NB*NT)
#define TPB 256
#define MTILE 128
#define LN_EPS 1e-3f

typedef unsigned long long u64;
typedef unsigned int u32;

// prepped weights: per var 9 tiles x 8192B (swizzled [n][k] bf16, 128B rows)
#define WPV_BYTES 73728
__device__ __align__(16) char g_wprep[NVARS * WPV_BYTES];

// tile byte offsets within a var block
#define WT_OFF 0
#define WP_HI 8192
#define WP_LO 16384
#define W1_HI 24576
#define W1_LO 32768
#define W2_HI 40960
#define W2_LO 49152
#define WG_HI 57344
#define WG_LO 65536
// smem byte offsets
#define WBUF0    0
#define WBUF1    73728
#define BIAS_ALL 147456      // 16 vars x 7 x 64 floats = 28672 B
#define CPROJ_O  176128      // 16 x 64 floats = 4096 B
#define WSEL_O   180224      // 128 x 16 floats = 8192 B
#define CTX_O    188416      // 64 floats
#define SMEM_TOTAL 188672

// ---------------- ptx helpers ----------------
__device__ __forceinline__ u32 smem_u32(const void* p) {
    u32 a;
    asm("{ .reg .u64 t; cvta.to.shared.u64 t, %1; cvt.u32.u64 %0, t; }"
        : "=r"(a) : "l"(p));
    return a;
}

#define LDMX4(r0, r1, r2, r3, addr) \
    asm volatile("ldmatrix.sync.aligned.m8n8.x4.shared.b16 {%0,%1,%2,%3}, [%4];" \
                 : "=r"(r0), "=r"(r1), "=r"(r2), "=r"(r3) : "r"(addr))

#define CP_ASYNC16(dst, src) \
    asm volatile("cp.async.cg.shared.global [%0], [%1], 16;" :: "r"(dst), "l"(src))
#define CP_COMMIT() asm volatile("cp.async.commit_group;")
#define CP_WAIT1() asm volatile("cp.async.wait_group 1;")
#define CP_WAIT0() asm volatile("cp.async.wait_group 0;")

__device__ __forceinline__ void mma16816(float* d, u32 a0, u32 a1, u32 a2, u32 a3,
                                         u32 b0, u32 b1) {
    asm volatile(
        "mma.sync.aligned.m16n8k16.row.col.f32.bf16.bf16.f32 "
        "{%0,%1,%2,%3},{%4,%5,%6,%7},{%8,%9},{%0,%1,%2,%3};"
        : "+f"(d[0]), "+f"(d[1]), "+f"(d[2]), "+f"(d[3])
        : "r"(a0), "r"(a1), "r"(a2), "r"(a3), "r"(b0), "r"(b1));
}

__device__ __forceinline__ u32 pkpair(float e0, float e1) {
    u32 r;
    asm("cvt.rn.bf16x2.f32 %0, %1, %2;" : "=r"(r) : "f"(e1), "f"(e0));
    return r;
}
__device__ __forceinline__ u32 pklo(u32 h, float e0, float e1) {
    float h0 = __uint_as_float(h << 16);
    float h1 = __uint_as_float(h & 0xffff0000u);
    return pkpair(e0 - h0, e1 - h1);
}
__device__ __forceinline__ float flo(u32 r) { return __uint_as_float(r << 16); }
__device__ __forceinline__ float fhi(u32 r) { return __uint_as_float(r & 0xffff0000u); }

__device__ __forceinline__ float sigm(float x) {
    return __fdividef(1.f, 1.f + __expf(-x));
}

__device__ __forceinline__ void d_to_frag(const float* D, u32* fh, u32* fl) {
#pragma unroll
    for (int kt = 0; kt < 4; kt++) {
        const float* d0 = D + (2 * kt) * 4;
        const float* d1 = D + (2 * kt + 1) * 4;
        u32 h;
        h = pkpair(d0[0], d0[1]); fh[4*kt+0] = h; fl[4*kt+0] = pklo(h, d0[0], d0[1]);
        h = pkpair(d0[2], d0[3]); fh[4*kt+1] = h; fl[4*kt+1] = pklo(h, d0[2], d0[3]);
        h = pkpair(d1[0], d1[1]); fh[4*kt+2] = h; fl[4*kt+2] = pklo(h, d1[0], d1[1]);
        h = pkpair(d1[2], d1[3]); fh[4*kt+3] = h; fl[4*kt+3] = pklo(h, d1[2], d1[3]);
    }
}

__device__ __forceinline__ void d_init(float* D, const float* bvec, int tig) {
#pragma unroll
    for (int j = 0; j < 8; j++) {
        float2 bv = *(const float2*)(bvec + 8 * j + 2 * tig);
        D[4*j+0] = bv.x; D[4*j+1] = bv.y; D[4*j+2] = bv.x; D[4*j+3] = bv.y;
    }
}

// D += (Ahi+Alo)@(Whi+Wlo)^T, accumulator chains interleaved (dep distance 2)
__device__ __forceinline__ void do_layer(u32 base_hi, u32 base_lo,
                                         const u32* fh, const u32* fl,
                                         float* D, int rowin, int m) {
    const u32 sw = (u32)(rowin << 4);
    const u32 rb = (u32)((m >> 1) * 1024 + rowin * 128);
#pragma unroll
    for (int kt = 0; kt < 4; kt++) {
        u32 csw = ((u32)(32 * kt + 16 * (m & 1))) ^ sw;
        const u32* ah = fh + 4 * kt;
        const u32* al = fl + 4 * kt;
#pragma unroll
        for (int p = 0; p < 4; p++) {
            u32 off = rb + (u32)(p * 2048) + csw;
            u32 bh0, bh1, bh2, bh3, bl0, bl1, bl2, bl3;
            LDMX4(bh0, bh1, bh2, bh3, base_hi + off);
            LDMX4(bl0, bl1, bl2, bl3, base_lo + off);
            mma16816(D + 8*p,     ah[0], ah[1], ah[2], ah[3], bh0, bh1);
            mma16816(D + 8*p + 4, ah[0], ah[1], ah[2], ah[3], bh2, bh3);
            mma16816(D + 8*p,     ah[0], ah[1], ah[2], ah[3], bl0, bl1);
            mma16816(D + 8*p + 4, ah[0], ah[1], ah[2], ah[3], bl2, bl3);
            mma16816(D + 8*p,     al[0], al[1], al[2], al[3], bh0, bh1);
            mma16816(D + 8*p + 4, al[0], al[1], al[2], al[3], bh2, bh3);
        }
    }
}

__device__ __forceinline__ void prefetch_var(u32 dst, const char* src, int tid) {
#pragma unroll
    for (int i = 0; i < 18; i++) {
        int idx = (tid + i * 256) * 16;
        CP_ASYNC16(dst + (u32)idx, src + idx);
    }
}

// ---------------------------------------------------------------------------
// prep: transpose + hi/lo split weights into swizzled [n][k] tiles
// ---------------------------------------------------------------------------
__global__ void prep_weights_kernel(const float* __restrict__ Wt,
                                    const float* __restrict__ Wp,
                                    const float* __restrict__ W1,
                                    const float* __restrict__ W2,
                                    const float* __restrict__ Wg) {
    int n = blockIdx.x;
    char* dst = g_wprep + (size_t)n * WPV_BYTES;
    for (int e = threadIdx.x; e < VDIM * DD; e += blockDim.x) {
        int d = e & 63, v = e >> 6;
        float w = Wt[(size_t)n * VDIM * DD + v * DD + d];
        __nv_bfloat16 hb = __float2bfloat16(w);
        __nv_bfloat16 lb = __float2bfloat16(w - __bfloat162float(hb));
        u32 cs = (u32)(16 * (v >> 3));
        u32 swx = ((u32)(d & 7)) << 4;
        u32 base = (u32)(d * 128) + (u32)((v & 7) * 2);
        *(__nv_bfloat16*)(dst + WT_OFF + base + (cs ^ swx)) = hb;
        *(__nv_bfloat16*)(dst + WT_OFF + base + ((cs + 32) ^ swx)) = lb;
    }
    const float* srcs[4] = {Wp + (size_t)n * DD * DD, W1 + (size_t)n * DD * DD,
                            W2 + (size_t)n * DD * DD, Wg + (size_t)n * DD * DD};
    const int hioff[4] = {WP_HI, W1_HI, W2_HI, WG_HI};
    for (int mm = 0; mm < 4; mm++) {
        const float* s = srcs[mm];
        char* th = dst + hioff[mm];
        char* tl = th + 8192;
        for (int e = threadIdx.x; e < DD * DD; e += blockDim.x) {
            int d = e & 63, k = e >> 6;
            float w = s[k * DD + d];
            __nv_bfloat16 hb = __float2bfloat16(w);
            __nv_bfloat16 lb = __float2bfloat16(w - __bfloat162float(hb));
            u32 cs = (u32)(16 * (k >> 3));
            u32 swx = ((u32)(d & 7)) << 4;
            u32 addr = (u32)(d * 128) + (cs ^ swx) + (u32)((k & 7) * 2);
            *(__nv_bfloat16*)(th + addr) = hb;
            *(__nv_bfloat16*)(tl + addr) = lb;
        }
    }
}

// ---------------------------------------------------------------------------
// main: fused softmax+cproj prologue, double-buffered weights, mma.sync chain
// ---------------------------------------------------------------------------
__global__ __launch_bounds__(TPB, 1) void vsn_mma_kernel(
    const float* __restrict__ inputs, const float* __restrict__ context,
    const float* __restrict__ Wctx,
    const float* __restrict__ bt, const float* __restrict__ b1,
    const float* __restrict__ b2, const float* __restrict__ bg,
    const float* __restrict__ bp,
    const float* __restrict__ gamma_, const float* __restrict__ beta_,
    const float* __restrict__ Ws, const float* __restrict__ bs,
    float* __restrict__ wout, float* __restrict__ selected) {
    extern __shared__ __align__(128) char sm[];
    const int tid = threadIdx.x;
    const int wid = tid >> 5, lane = tid & 31;
    const int gid = lane >> 2, tig = lane & 3;
    const int rowin = lane & 7, mq = lane >> 3;
    const int row0 = wid * 16 + gid, row1 = row0 + 8;
    const int base = blockIdx.x * MTILE;
    const int bb = base / NT;
    const int tok0 = base + row0, tok1 = base + row1;

    const u32 smb = smem_u32(sm);
    float* bias_all = (float*)(sm + BIAS_ALL);
    float* cproj_s = (float*)(sm + CPROJ_O);
    float* wsel_s  = (float*)(sm + WSEL_O);
    float* ctx_s   = (float*)(sm + CTX_O);

    // prefetch var 0 weights immediately (WBUF0 untouched by prologue)
    prefetch_var(smb + WBUF0, g_wprep, tid);
    CP_COMMIT();

    // stage Ws (into WBUF1, free until var-1 prefetch) and ctx
    {
        const float4* s = (const float4*)Ws;
        float4* d = (float4*)(sm + WBUF1);
        for (int i = tid; i < 1024; i += TPB) d[i] = s[i];
        if (tid < DD) ctx_s[tid] = context[(size_t)bb * DD + tid];
    }
    // stage all biases [16][7][64]
    {
        const float* bsrc[7] = {bt, b1, b2, bg, bp, gamma_, beta_};
        for (int i = tid; i < NVARS * 7 * DD; i += TPB) {
            int n = i / 448, r = i - n * 448, s = r >> 6, d = r & 63;
            bias_all[i] = bsrc[s][n * DD + d];
        }
    }
    __syncthreads();

    if (tid < 128) {
        // softmax for token base+tid
        int token = base + tid;
        const float4* xp = (const float4*)(inputs + (size_t)token * 256);
        const float* ws_s = (const float*)(sm + WBUF1);
        float l[16];
#pragma unroll
        for (int i = 0; i < 16; i++) l[i] = bs[i];
#pragma unroll 4
        for (int f4 = 0; f4 < 64; ++f4) {
            float4 xv = xp[f4];
            const float* wr = ws_s + f4 * 64;
#pragma unroll
            for (int c = 0; c < 4; c++) {
                float x = (c == 0) ? xv.x : (c == 1) ? xv.y : (c == 2) ? xv.z : xv.w;
                const float* w = wr + c * 16;
#pragma unroll
                for (int i = 0; i < 16; i++) l[i] = fmaf(x, w[i], l[i]);
            }
        }
        float mx = l[0];
#pragma unroll
        for (int i = 1; i < 16; i++) mx = fmaxf(mx, l[i]);
        float s = 0.f;
#pragma unroll
        for (int i = 0; i < 16; i++) { l[i] = __expf(l[i] - mx); s += l[i]; }
        float inv = __fdividef(1.f, s);
        float4* gp = (float4*)(wout + (size_t)token * 16);
        float4* sp = (float4*)(wsel_s + tid * 16);
#pragma unroll
        for (int j = 0; j < 4; j++) {
            float4 o = make_float4(l[4*j] * inv, l[4*j+1] * inv,
                                   l[4*j+2] * inv, l[4*j+3] * inv);
            gp[j] = o;
            sp[j] = o;
        }
    } else {
        // cproj: 128 threads x 8 outputs
        int idx = tid - 128;
        int n = idx >> 3, e0 = (idx & 7) * 8;
        const float* W = Wctx + (size_t)n * DD * DD + e0;
        float acc[8];
#pragma unroll
        for (int i = 0; i < 8; i++) acc[i] = 0.f;
#pragma unroll 8
        for (int d = 0; d < DD; ++d) {
            float c = ctx_s[d];
            float4 w0 = *(const float4*)(W + d * DD);
            float4 w1 = *(const float4*)(W + d * DD + 4);
            acc[0] = fmaf(c, w0.x, acc[0]); acc[1] = fmaf(c, w0.y, acc[1]);
            acc[2] = fmaf(c, w0.z, acc[2]); acc[3] = fmaf(c, w0.w, acc[3]);
            acc[4] = fmaf(c, w1.x, acc[4]); acc[5] = fmaf(c, w1.y, acc[5]);
            acc[6] = fmaf(c, w1.z, acc[6]); acc[7] = fmaf(c, w1.w, acc[7]);
        }
        float4* cp = (float4*)(cproj_s + n * DD + e0);
        cp[0] = make_float4(acc[0], acc[1], acc[2], acc[3]);
        cp[1] = make_float4(acc[4], acc[5], acc[6], acc[7]);
    }
    __syncthreads();   // prologue done; WBUF1 free for var-1 prefetch

    float sel[32];
#pragma unroll
    for (int i = 0; i < 32; i++) sel[i] = 0.f;

    for (int n = 0; n < NVARS; ++n) {
        if (n < NVARS - 1) {
            prefetch_var(smb + (((n + 1) & 1) ? WBUF1 : WBUF0),
                         g_wprep + (size_t)(n + 1) * WPV_BYTES, tid);
            CP_COMMIT();
            CP_WAIT1();
        } else {
            CP_WAIT0();
        }
        __syncthreads();   // buf[n&1] ready

        const u32 wb = smb + ((n & 1) ? WBUF1 : WBUF0);
        const float* bv = bias_all + n * 448;

        // ---- layer 1: t = x @ Wt + bt (k=16) ----
        float D[32];
        d_init(D, bv + 0 * DD, tig);
        {
            const float* xb0 = inputs + (size_t)tok0 * 256 + n * VDIM;
            const float* xb1 = inputs + (size_t)tok1 * 256 + n * VDIM;
            float2 x00 = *(const float2*)(xb0 + 2 * tig);
            float2 x10 = *(const float2*)(xb1 + 2 * tig);
            float2 x01 = *(const float2*)(xb0 + 8 + 2 * tig);
            float2 x11 = *(const float2*)(xb1 + 8 + 2 * tig);
            u32 axh[4], axl[4];
            axh[0] = pkpair(x00.x, x00.y); axl[0] = pklo(axh[0], x00.x, x00.y);
            axh[1] = pkpair(x10.x, x10.y); axl[1] = pklo(axh[1], x10.x, x10.y);
            axh[2] = pkpair(x01.x, x01.y); axl[2] = pklo(axh[2], x01.x, x01.y);
            axh[3] = pkpair(x11.x, x11.y); axl[3] = pklo(axh[3], x11.x, x11.y);

            const u32 sw = (u32)(rowin << 4);
            const u32 rb = (u32)((mq >> 1) * 1024 + rowin * 128);
            u32 csh = ((u32)(16 * (mq & 1))) ^ sw;
            u32 csl = ((u32)(32 + 16 * (mq & 1))) ^ sw;
#pragma unroll
            for (int p = 0; p < 4; p++) {
                u32 off = rb + (u32)(p * 2048);
                u32 bh0, bh1, bh2, bh3, bl0, bl1, bl2, bl3;
                LDMX4(bh0, bh1, bh2, bh3, wb + WT_OFF + off + csh);
                LDMX4(bl0, bl1, bl2, bl3, wb + WT_OFF + off + csl);
                mma16816(D + 8*p,     axh[0], axh[1], axh[2], axh[3], bh0, bh1);
                mma16816(D + 8*p + 4, axh[0], axh[1], axh[2], axh[3], bh2, bh3);
                mma16816(D + 8*p,     axh[0], axh[1], axh[2], axh[3], bl0, bl1);
                mma16816(D + 8*p + 4, axh[0], axh[1], axh[2], axh[3], bl2, bl3);
                mma16816(D + 8*p,     axl[0], axl[1], axl[2], axl[3], bh0, bh1);
                mma16816(D + 8*p + 4, axl[0], axl[1], axl[2], axl[3], bh2, bh3);
            }
        }

        u32 fh[16], fl[16];
        d_to_frag(D, fh, fl);      // t fragments

        // ---- residual = t @ Wp + bp ----
        float Dres[32];
        d_init(Dres, bv + 4 * DD, tig);
        do_layer(wb + WP_HI, wb + WP_LO, fh, fl, Dres, rowin, mq);

        // ---- a = t + cproj ----
#pragma unroll
        for (int j = 0; j < 8; j++) {
            float2 cp = *(const float2*)(cproj_s + n * DD + 8 * j + 2 * tig);
            D[4*j+0] += cp.x; D[4*j+1] += cp.y;
            D[4*j+2] += cp.x; D[4*j+3] += cp.y;
        }
        d_to_frag(D, fh, fl);

        // ---- h1 = elu(a @ W1 + b1) ----
        d_init(D, bv + 1 * DD, tig);
        do_layer(wb + W1_HI, wb + W1_LO, fh, fl, D, rowin, mq);
#pragma unroll
        for (int i = 0; i < 32; i++) {
            float x = D[i];
            D[i] = x > 0.f ? x : (__expf(x) - 1.f);
        }
        d_to_frag(D, fh, fl);

        // ---- h2 = h1 @ W2 + b2 ----
        d_init(D, bv + 2 * DD, tig);
        do_layer(wb + W2_HI, wb + W2_LO, fh, fl, D, rowin, mq);
        d_to_frag(D, fh, fl);      // h2 fragments

        // ---- gate logits = h2 @ Wg + bg ----
        d_init(D, bv + 3 * DD, tig);
        do_layer(wb + WG_HI, wb + WG_LO, fh, fl, D, rowin, mq);

        // ---- y, LN, weighted select ----
        float sum0 = 0.f, sq0 = 0.f, sum1 = 0.f, sq1 = 0.f;
#pragma unroll
        for (int j = 0; j < 8; j++) {
            int o = 4 * (j >> 1) + 2 * (j & 1);
            u32 h0 = fh[o], l0 = fl[o], h1r = fh[o + 1], l1r = fl[o + 1];
            float h2a = flo(h0) + flo(l0), h2b = fhi(h0) + fhi(l0);
            float h2c = flo(h1r) + flo(l1r), h2d = fhi(h1r) + fhi(l1r);
            float y0 = fmaf(sigm(D[4*j+0]), h2a, Dres[4*j+0]);
            float y1 = fmaf(sigm(D[4*j+1]), h2b, Dres[4*j+1]);
            float y2 = fmaf(sigm(D[4*j+2]), h2c, Dres[4*j+2]);
            float y3 = fmaf(sigm(D[4*j+3]), h2d, Dres[4*j+3]);
            D[4*j+0] = y0; D[4*j+1] = y1; D[4*j+2] = y2; D[4*j+3] = y3;
            sum0 += y0 + y1; sq0 = fmaf(y0, y0, fmaf(y1, y1, sq0));
            sum1 += y2 + y3; sq1 = fmaf(y2, y2, fmaf(y3, y3, sq1));
        }
        sum0 += __shfl_xor_sync(0xffffffffu, sum0, 1);
        sum0 += __shfl_xor_sync(0xffffffffu, sum0, 2);
        sq0  += __shfl_xor_sync(0xffffffffu, sq0, 1);
        sq0  += __shfl_xor_sync(0xffffffffu, sq0, 2);
        sum1 += __shfl_xor_sync(0xffffffffu, sum1, 1);
        sum1 += __shfl_xor_sync(0xffffffffu, sum1, 2);
        sq1  += __shfl_xor_sync(0xffffffffu, sq1, 1);
        sq1  += __shfl_xor_sync(0xffffffffu, sq1, 2);
        float mu0 = sum0 * (1.f / 64.f);
        float rs0 = rsqrtf(sq0 * (1.f / 64.f) - mu0 * mu0 + LN_EPS);
        float mu1 = sum1 * (1.f / 64.f);
        float rs1 = rsqrtf(sq1 * (1.f / 64.f) - mu1 * mu1 + LN_EPS);
        float w0 = wsel_s[row0 * NVARS + n];
        float w1 = wsel_s[row1 * NVARS + n];
#pragma unroll
        for (int j = 0; j < 8; j++) {
            float2 gm = *(const float2*)(bv + 5 * DD + 8 * j + 2 * tig);
            float2 be = *(const float2*)(bv + 6 * DD + 8 * j + 2 * tig);
            float yn0 = fmaf((D[4*j+0] - mu0) * rs0, gm.x, be.x);
            float yn1 = fmaf((D[4*j+1] - mu0) * rs0, gm.y, be.y);
            float yn2 = fmaf((D[4*j+2] - mu1) * rs1, gm.x, be.x);
            float yn3 = fmaf((D[4*j+3] - mu1) * rs1, gm.y, be.y);
            sel[4*j+0] = fmaf(w0, yn0, sel[4*j+0]);
            sel[4*j+1] = fmaf(w0, yn1, sel[4*j+1]);
            sel[4*j+2] = fmaf(w1, yn2, sel[4*j+2]);
            sel[4*j+3] = fmaf(w1, yn3, sel[4*j+3]);
        }
        __syncthreads();   // reads of buf[n&1] done before it is re-prefetched
    }

    // ---- output ----
#pragma unroll
    for (int j = 0; j < 8; j++) {
        *(float2*)(selected + (size_t)tok0 * DD + 8 * j + 2 * tig)
            = make_float2(sel[4*j+0], sel[4*j+1]);
        *(float2*)(selected + (size_t)tok1 * DD + 8 * j + 2 * tig)
            = make_float2(sel[4*j+2], sel[4*j+3]);
    }
}

// ---------------------------------------------------------------------------
extern "C" void kernel_launch(void* const* d_in, const int* in_sizes, int n_in,
                              void* d_out, int out_size) {
    const float* inputs  = (const float*)d_in[0];
    const float* context = (const float*)d_in[1];
    const float* Wt   = (const float*)d_in[2];
    const float* bt   = (const float*)d_in[3];
    const float* Wctx = (const float*)d_in[4];
    const float* W1   = (const float*)d_in[5];
    const float* b1   = (const float*)d_in[6];
    const float* W2   = (const float*)d_in[7];
    const float* b2   = (const float*)d_in[8];
    const float* Wg   = (const float*)d_in[9];
    const float* bg   = (const float*)d_in[10];
    const float* Wp   = (const float*)d_in[11];
    const float* bp   = (const float*)d_in[12];
    const float* gam  = (const float*)d_in[13];
    const float* bet  = (const float*)d_in[14];
    const float* Ws   = (const float*)d_in[15];
    const float* bs   = (const float*)d_in[16];

    float* selected = (float*)d_out;
    float* wout = selected + (size_t)NTOK * DD;

    prep_weights_kernel<<<NVARS, 256>>>(Wt, Wp, W1, W2, Wg);

    cudaFuncSetAttribute(vsn_mma_kernel,
                         cudaFuncAttributeMaxDynamicSharedMemorySize, SMEM_TOTAL);
    vsn_mma_kernel<<<NTOK / MTILE, TPB, SMEM_TOTAL>>>(
        inputs, context, Wctx, bt, b1, b2, bg, bp, gam, bet, Ws, bs,
        wout, selected);
}